// round 16
// baseline (speedup 1.0000x reference)
#include <cuda_runtime.h>
#include <cuda_bf16.h>
#include <math_constants.h>

// Problem constants
#define BB 16
#define CC 3
#define MM 512
#define NN 512
#define MNP (MM * NN)                 // 262144 pixels per (b, c) plane
#define PIX (BB * MNP)                // 4,194,304 pixels
#define THREADS1 256
#define PIX_PER_THREAD 8              // two 4-px sub-tiles
#define PIX_PER_BLOCK (THREADS1 * PIX_PER_THREAD)     // 2048
#define BLOCKS1 (PIX / PIX_PER_BLOCK)                 // 2048
#define EPS_F 1e-6f
#define T1_CLIP_F 1e7f

// Fixed scratch for block partials (no allocation allowed)
__device__ float g_psum[BLOCKS1];
__device__ float g_pmax[BLOCKS1];
__device__ unsigned int g_count = 0;

__device__ __forceinline__ float rcp_approx(float x) {
    float y;
    asm("rcp.approx.f32 %0, %1;" : "=f"(y) : "f"(x));
    return y;
}

// Streaming 128-bit global load
__device__ __forceinline__ float4 ldcs4(const float* p) {
    return __ldcs(reinterpret_cast<const float4*>(p));
}

// Issue one warp-tile (128 px) of sigma as 9 coalesced 16B cp.async + commit.
__device__ __forceinline__ void sigma_cp(const float* __restrict__ sigma_y,
                                         int pixBase, float* slab, int lane)
{
    const float* src = sigma_y + (size_t)pixBase * 9;       // 4608 B
    unsigned sw = (unsigned)__cvta_generic_to_shared(slab);
#pragma unroll
    for (int k = 0; k < 9; k++) {
        const int f4 = k * 32 + lane;
        asm volatile("cp.async.cg.shared.global [%0], [%1], 16;"
                     :: "r"(sw + f4 * 16), "l"(src + f4 * 4) : "memory");
    }
    asm volatile("cp.async.commit_group;" ::: "memory");
}

// Compute one 4-px sub-tile from its smem slab + prefetched diffs.
__device__ __forceinline__ void tile_math(const float* slab, int lane,
                                          const float* dx, const float* dy,
                                          const float* dz,
                                          float& sumv, float& maxv)
{
    // Thread's 36 sigma floats: word offset 36*lane (144B stride, 16B aligned
    // -> 9 LDS.128, bank-conflict-free per phase).
    const float4* s4 = reinterpret_cast<const float4*>(slab + lane * 36);
    float4 sv[9];
#pragma unroll
    for (int i = 0; i < 9; i++) sv[i] = s4[i];
    const float* sf = reinterpret_cast<const float*>(sv);

    float qv[4], dc[4];
#pragma unroll
    for (int j = 0; j < 4; j++) {
        const float* s = sf + 9 * j;   // row-major symmetric 3x3
        const float a  = s[0], bq = s[1], c = s[2];
        const float d  = s[4], e  = s[5];
        const float f  = s[8];

        const float A00 = fmaf(d, f, -e * e);
        const float A01 = fmaf(c, e, -bq * f);
        const float A02 = fmaf(bq, e, -c * d);
        const float A11 = fmaf(a, f, -c * c);
        const float A12 = fmaf(bq, c, -a * e);
        const float A22 = fmaf(a, d, -bq * bq);

        const float det = fmaf(a, A00, fmaf(bq, A01, c * A02));

        const float x = dx[j], y = dy[j], z = dz[j];
        float q = x * x * A00;
        q = fmaf(y * y, A11, q);
        q = fmaf(z * z, A22, q);
        float cross = x * y * A01;
        cross = fmaf(x * z, A02, cross);
        cross = fmaf(y * z, A12, cross);
        q = fmaf(2.0f, cross, q);

        qv[j] = q;
        dc[j] = fmaxf(det, EPS_F);   // SPD (>= 0.5 I) => clamp never binds
    }

    const float p01  = dc[0] * dc[1];
    const float p23  = dc[2] * dc[3];
    const float prod = p01 * p23;
    const float invp = rcp_approx(prod);

    const float t1v0 = 0.5f * qv[0] * (dc[1] * p23 * invp);
    const float t1v1 = 0.5f * qv[1] * (dc[0] * p23 * invp);
    const float t1v2 = 0.5f * qv[2] * (p01 * dc[3] * invp);
    const float t1v3 = 0.5f * qv[3] * (p01 * dc[2] * invp);

    sumv += (t1v0 + t1v1) + (t1v2 + t1v3) + 0.5f * __logf(prod);
    maxv  = fmaxf(maxv, fmaxf(fmaxf(t1v0, t1v1), fmaxf(t1v2, t1v3)));
}

__global__ __launch_bounds__(THREADS1) void maploss_main(
    const float* __restrict__ target,
    const float* __restrict__ mu,
    const float* __restrict__ sigma_y,
    float* __restrict__ out)
{
    // 8 warps * 2 sub-tiles * 128 px * 9 floats = 72 KB sigma staging
    __shared__ float s_sig[2][8 * 128 * 9];

    const int tid  = threadIdx.x;
    const int lane = tid & 31;
    const int wid  = tid >> 5;

    // Warp owns 256 consecutive pixels: sub-tile A = first 128, B = next 128.
    const int pixA = blockIdx.x * PIX_PER_BLOCK + wid * 256;
    const int pixB = pixA + 128;

    // ---- 1) t/mu wide loads for BOTH sub-tiles first (12 LDG.128 in flight) ----
    const int pA = pixA + lane * 4;
    const int bA = pA >> 18;
    const size_t baseA = (size_t)bA * (CC * MNP) + (pA & (MNP - 1));
    const int pB = pixB + lane * 4;
    const int bB = pB >> 18;
    const size_t baseB = (size_t)bB * (CC * MNP) + (pB & (MNP - 1));

    float4 tA0 = ldcs4(target + baseA);
    float4 uA0 = ldcs4(mu + baseA);
    float4 tA1 = ldcs4(target + baseA + MNP);
    float4 uA1 = ldcs4(mu + baseA + MNP);
    float4 tA2 = ldcs4(target + baseA + 2 * MNP);
    float4 uA2 = ldcs4(mu + baseA + 2 * MNP);

    float4 tB0 = ldcs4(target + baseB);
    float4 uB0 = ldcs4(mu + baseB);
    float4 tB1 = ldcs4(target + baseB + MNP);
    float4 uB1 = ldcs4(mu + baseB + MNP);
    float4 tB2 = ldcs4(target + baseB + 2 * MNP);
    float4 uB2 = ldcs4(mu + baseB + 2 * MNP);

    // ---- 2) sigma staging for both sub-tiles (2 commit groups) ----
    float* slabA = &s_sig[0][wid * (128 * 9)];
    float* slabB = &s_sig[1][wid * (128 * 9)];
    sigma_cp(sigma_y, pixA, slabA, lane);
    sigma_cp(sigma_y, pixB, slabB, lane);

    // Fold t/mu into differences (frees the float4 registers)
    const float dxA[4] = { tA0.x-uA0.x, tA0.y-uA0.y, tA0.z-uA0.z, tA0.w-uA0.w };
    const float dyA[4] = { tA1.x-uA1.x, tA1.y-uA1.y, tA1.z-uA1.z, tA1.w-uA1.w };
    const float dzA[4] = { tA2.x-uA2.x, tA2.y-uA2.y, tA2.z-uA2.z, tA2.w-uA2.w };
    const float dxB[4] = { tB0.x-uB0.x, tB0.y-uB0.y, tB0.z-uB0.z, tB0.w-uB0.w };
    const float dyB[4] = { tB1.x-uB1.x, tB1.y-uB1.y, tB1.z-uB1.z, tB1.w-uB1.w };
    const float dzB[4] = { tB2.x-uB2.x, tB2.y-uB2.y, tB2.z-uB2.z, tB2.w-uB2.w };

    float sumv = 0.0f;
    float maxv = -CUDART_INF_F;

    // ---- 3) compute A while B's copies drain, then B ----
    asm volatile("cp.async.wait_group 1;" ::: "memory");
    __syncwarp();
    tile_math(slabA, lane, dxA, dyA, dzA, sumv, maxv);

    asm volatile("cp.async.wait_group 0;" ::: "memory");
    __syncwarp();
    tile_math(slabB, lane, dxB, dyB, dzB, sumv, maxv);

    // ---- warp reduce ----
#pragma unroll
    for (int off = 16; off > 0; off >>= 1) {
        sumv += __shfl_down_sync(0xFFFFFFFFu, sumv, off);
        maxv  = fmaxf(maxv, __shfl_down_sync(0xFFFFFFFFu, maxv, off));
    }

    __shared__ float ssum[THREADS1 / 32];
    __shared__ float smax[THREADS1 / 32];
    if (lane == 0) { ssum[wid] = sumv; smax[wid] = maxv; }
    __syncthreads();

    if (wid == 0) {
        float s2 = (lane < THREADS1 / 32) ? ssum[lane] : 0.0f;
        float m2 = (lane < THREADS1 / 32) ? smax[lane] : -CUDART_INF_F;
#pragma unroll
        for (int off = 4; off > 0; off >>= 1) {
            s2 += __shfl_down_sync(0xFFFFFFFFu, s2, off);
            m2  = fmaxf(m2, __shfl_down_sync(0xFFFFFFFFu, m2, off));
        }
        if (lane == 0) {
            g_psum[blockIdx.x] = s2;
            g_pmax[blockIdx.x] = m2;
        }
    }

    // ---- fused finish: last block reduces all partials ----
    __shared__ bool is_last;
    __syncthreads();
    if (tid == 0) {
        __threadfence();        // publish this block's partials
        unsigned int old = atomicAdd(&g_count, 1u);
        is_last = (old == (unsigned int)(BLOCKS1 - 1));
    }
    __syncthreads();

    if (is_last) {
        if (tid == 0) __threadfence();  // acquire: see all partials
        __syncthreads();
        float s = 0.0f;
        float m = -CUDART_INF_F;
#pragma unroll
        for (int i = 0; i < BLOCKS1 / THREADS1; i++) {
            const int idx = tid + i * THREADS1;
            s += __ldcg(&g_psum[idx]);
            m  = fmaxf(m, __ldcg(&g_pmax[idx]));
        }
#pragma unroll
        for (int off = 16; off > 0; off >>= 1) {
            s += __shfl_down_sync(0xFFFFFFFFu, s, off);
            m  = fmaxf(m, __shfl_down_sync(0xFFFFFFFFu, m, off));
        }
        if (lane == 0) { ssum[wid] = s; smax[wid] = m; }
        __syncthreads();
        if (wid == 0) {
            float s2 = (lane < THREADS1 / 32) ? ssum[lane] : 0.0f;
            float m2 = (lane < THREADS1 / 32) ? smax[lane] : -CUDART_INF_F;
#pragma unroll
            for (int off = 4; off > 0; off >>= 1) {
                s2 += __shfl_down_sync(0xFFFFFFFFu, s2, off);
                m2  = fmaxf(m2, __shfl_down_sync(0xFFFFFFFFu, m2, off));
            }
            if (lane == 0) {
                const float mean = s2 * (1.0f / (float)PIX);
                out[0] = (m2 > T1_CLIP_F) ? 0.0f : mean;
                g_count = 0;   // reset ticket for next graph replay
            }
        }
    }
}

extern "C" void kernel_launch(void* const* d_in, const int* in_sizes, int n_in,
                              void* d_out, int out_size)
{
    // Input order per reference: target, mu, sigma_mu, sigma_n, sigma_y
    const float* target  = (const float*)d_in[0];
    const float* mu      = (const float*)d_in[1];
    const float* sigma_y = (const float*)d_in[4];
    float* out = (float*)d_out;

    maploss_main<<<BLOCKS1, THREADS1>>>(target, mu, sigma_y, out);
}

// round 17
// speedup vs baseline: 1.0482x; 1.0482x over previous
#include <cuda_runtime.h>
#include <cuda_bf16.h>
#include <math_constants.h>

// Problem constants
#define BB 16
#define CC 3
#define MM 512
#define NN 512
#define MNP (MM * NN)                 // 262144 pixels per (b, c) plane
#define PIX (BB * MNP)                // 4,194,304 pixels
#define THREADS1 256
#define PIX_PER_THREAD 4
#define PIX_PER_BLOCK (THREADS1 * PIX_PER_THREAD)     // 1024
#define BLOCKS1 (PIX / PIX_PER_BLOCK)                 // 4096
#define EPS_F 1e-6f
#define T1_CLIP_F 1e7f

// Fixed scratch for block partials (no allocation allowed)
__device__ float g_psum[BLOCKS1];
__device__ float g_pmax[BLOCKS1];
__device__ unsigned int g_count = 0;

__device__ __forceinline__ float rcp_approx(float x) {
    float y;
    asm("rcp.approx.f32 %0, %1;" : "=f"(y) : "f"(x));
    return y;
}

// Streaming 128-bit global load
__device__ __forceinline__ float4 ldcs4(const float* p) {
    return __ldcs(reinterpret_cast<const float4*>(p));
}

__global__ __launch_bounds__(THREADS1) void maploss_main(
    const float* __restrict__ target,
    const float* __restrict__ mu,
    const float* __restrict__ sigma_y,
    float* __restrict__ out)
{
    // Warp-owned sigma staging: 8 warps * 128 px * 9 floats = 36 KB
    __shared__ float s_sig[THREADS1 * 9 * PIX_PER_THREAD];

    const int tid  = threadIdx.x;
    const int lane = tid & 31;
    const int wid  = tid >> 5;

    // Warp tile: 128 consecutive pixels; thread owns 4 CONSECUTIVE pixels.
    const int warpPixBase = blockIdx.x * PIX_PER_BLOCK + wid * 128;

    // ---- 1) t/mu wide loads FIRST (longest latency into the L1tex queue) ----
    const int p0 = warpPixBase + lane * PIX_PER_THREAD;
    const int b  = p0 >> 18;
    const int r  = p0 & (MNP - 1);
    const size_t base = (size_t)b * (CC * MNP) + r;

    float4 t0 = ldcs4(target + base);
    float4 u0 = ldcs4(mu + base);
    float4 t1 = ldcs4(target + base + MNP);
    float4 u1 = ldcs4(mu + base + MNP);
    float4 t2 = ldcs4(target + base + 2 * MNP);
    float4 u2 = ldcs4(mu + base + 2 * MNP);

    // ---- 2) cp.async staging of sigma (coalesced 16B chunks) ----
    {
        const float* src = sigma_y + (size_t)warpPixBase * 9;   // 4608 B / warp
        unsigned smem_w = (unsigned)__cvta_generic_to_shared(
            &s_sig[wid * (128 * 9)]);
#pragma unroll
        for (int k = 0; k < 9; k++) {
            const int f4 = k * 32 + lane;
            asm volatile("cp.async.cg.shared.global [%0], [%1], 16;"
                         :: "r"(smem_w + f4 * 16), "l"(src + f4 * 4) : "memory");
        }
        asm volatile("cp.async.commit_group;" ::: "memory");
    }

    // Fold t/mu into differences ASAP (frees 12 registers before the wait)
    const float dx[4] = { t0.x - u0.x, t0.y - u0.y, t0.z - u0.z, t0.w - u0.w };
    const float dy[4] = { t1.x - u1.x, t1.y - u1.y, t1.z - u1.z, t1.w - u1.w };
    const float dz[4] = { t2.x - u2.x, t2.y - u2.y, t2.z - u2.z, t2.w - u2.w };

    // ---- 3) wait for sigma; per-thread 144B slab via LDS.128 (conflict-free) ----
    asm volatile("cp.async.wait_group 0;" ::: "memory");
    __syncwarp();

    // Thread's 36 sigma floats start at word 36*lane within the warp slab
    // (144B stride, 16B aligned -> 9 LDS.128, bank-conflict-free per phase).
    const float4* s4 = reinterpret_cast<const float4*>(
        &s_sig[wid * (128 * 9) + lane * 36]);
    float4 sv[9];
#pragma unroll
    for (int i = 0; i < 9; i++) sv[i] = s4[i];
    const float* sf = reinterpret_cast<const float*>(sv);

    float qv[4], dc[4];
#pragma unroll
    for (int j = 0; j < 4; j++) {
        const float* s = sf + 9 * j;   // row-major symmetric 3x3
        const float a  = s[0], bq = s[1], c = s[2];
        const float d  = s[4], e  = s[5];
        const float f  = s[8];

        const float A00 = fmaf(d, f, -e * e);
        const float A01 = fmaf(c, e, -bq * f);
        const float A02 = fmaf(bq, e, -c * d);
        const float A11 = fmaf(a, f, -c * c);
        const float A12 = fmaf(bq, c, -a * e);
        const float A22 = fmaf(a, d, -bq * bq);

        const float det = fmaf(a, A00, fmaf(bq, A01, c * A02));

        const float x = dx[j], y = dy[j], z = dz[j];
        float q = x * x * A00;
        q = fmaf(y * y, A11, q);
        q = fmaf(z * z, A22, q);
        float cross = x * y * A01;
        cross = fmaf(x * z, A02, cross);
        cross = fmaf(y * z, A12, cross);
        q = fmaf(2.0f, cross, q);

        qv[j] = q;
        dc[j] = fmaxf(det, EPS_F);   // SPD (>= 0.5 I) => clamp never binds
    }

    // ---- batched reciprocal + batched log: 1 RCP + 1 LG2 per 4 pixels ----
    const float p01  = dc[0] * dc[1];
    const float p23  = dc[2] * dc[3];
    const float prod = p01 * p23;
    const float invp = rcp_approx(prod);

    const float t1v0 = 0.5f * qv[0] * (dc[1] * p23 * invp);
    const float t1v1 = 0.5f * qv[1] * (dc[0] * p23 * invp);
    const float t1v2 = 0.5f * qv[2] * (p01 * dc[3] * invp);
    const float t1v3 = 0.5f * qv[3] * (p01 * dc[2] * invp);

    float sumv = (t1v0 + t1v1) + (t1v2 + t1v3) + 0.5f * __logf(prod);
    float maxv = fmaxf(fmaxf(t1v0, t1v1), fmaxf(t1v2, t1v3));

    // ---- warp reduce ----
#pragma unroll
    for (int off = 16; off > 0; off >>= 1) {
        sumv += __shfl_down_sync(0xFFFFFFFFu, sumv, off);
        maxv  = fmaxf(maxv, __shfl_down_sync(0xFFFFFFFFu, maxv, off));
    }

    __shared__ float ssum[THREADS1 / 32];
    __shared__ float smax[THREADS1 / 32];
    if (lane == 0) { ssum[wid] = sumv; smax[wid] = maxv; }
    __syncthreads();

    if (wid == 0) {
        float s2 = (lane < THREADS1 / 32) ? ssum[lane] : 0.0f;
        float m2 = (lane < THREADS1 / 32) ? smax[lane] : -CUDART_INF_F;
#pragma unroll
        for (int off = 4; off > 0; off >>= 1) {
            s2 += __shfl_down_sync(0xFFFFFFFFu, s2, off);
            m2  = fmaxf(m2, __shfl_down_sync(0xFFFFFFFFu, m2, off));
        }
        if (lane == 0) {
            g_psum[blockIdx.x] = s2;
            g_pmax[blockIdx.x] = m2;
        }
    }

    // ---- fused finish: last block reduces all partials ----
    __shared__ bool is_last;
    __syncthreads();
    if (tid == 0) {
        __threadfence();        // publish this block's partials
        unsigned int old = atomicAdd(&g_count, 1u);
        is_last = (old == (unsigned int)(BLOCKS1 - 1));
    }
    __syncthreads();

    if (is_last) {
        if (tid == 0) __threadfence();  // acquire: see all partials
        __syncthreads();
        float s = 0.0f;
        float m = -CUDART_INF_F;
#pragma unroll
        for (int i = 0; i < BLOCKS1 / THREADS1; i++) {
            const int idx = tid + i * THREADS1;
            s += __ldcg(&g_psum[idx]);
            m  = fmaxf(m, __ldcg(&g_pmax[idx]));
        }
#pragma unroll
        for (int off = 16; off > 0; off >>= 1) {
            s += __shfl_down_sync(0xFFFFFFFFu, s, off);
            m  = fmaxf(m, __shfl_down_sync(0xFFFFFFFFu, m, off));
        }
        if (lane == 0) { ssum[wid] = s; smax[wid] = m; }
        __syncthreads();
        if (wid == 0) {
            float s2 = (lane < THREADS1 / 32) ? ssum[lane] : 0.0f;
            float m2 = (lane < THREADS1 / 32) ? smax[lane] : -CUDART_INF_F;
#pragma unroll
            for (int off = 4; off > 0; off >>= 1) {
                s2 += __shfl_down_sync(0xFFFFFFFFu, s2, off);
                m2  = fmaxf(m2, __shfl_down_sync(0xFFFFFFFFu, m2, off));
            }
            if (lane == 0) {
                const float mean = s2 * (1.0f / (float)PIX);
                out[0] = (m2 > T1_CLIP_F) ? 0.0f : mean;
                g_count = 0;   // reset ticket for next graph replay
            }
        }
    }
}

extern "C" void kernel_launch(void* const* d_in, const int* in_sizes, int n_in,
                              void* d_out, int out_size)
{
    // Input order per reference: target, mu, sigma_mu, sigma_n, sigma_y
    const float* target  = (const float*)d_in[0];
    const float* mu      = (const float*)d_in[1];
    const float* sigma_y = (const float*)d_in[4];
    float* out = (float*)d_out;

    maploss_main<<<BLOCKS1, THREADS1>>>(target, mu, sigma_y, out);
}